// round 4
// baseline (speedup 1.0000x reference)
#include <cuda_runtime.h>
#include <cstdint>

// Problem constants (fixed shapes from setup_inputs)
#define TT 64
#define BB 4096
#define DD 32
#define HH 5
#define GG 20      // 4*H gates
#define VV 10
#define IN 128

#define BLK 256
#define NCHUNK (BB / BLK)   // 16 b-chunks

// Per-b precomputed terms (transposed [g][B] for coalesced access), L2-resident.
__device__ float g_hb0[GG * BB];
__device__ float g_hb1[GG * BB];
__device__ float g_c0[HH * BB];
__device__ float g_c1[HH * BB];

__device__ __forceinline__ float sigm(float v) {
    return __fdividef(1.0f, 1.0f + __expf(-v));
}
__device__ __forceinline__ float tanh_(float v) {
    // tanh(x) = 1 - 2/(e^{2x}+1); robust at +/-inf with __fdividef
    return 1.0f - __fdividef(2.0f, __expf(2.0f * v) + 1.0f);
}

// ---------------------------------------------------------------------------
// Kernel 1: per-b precompute of h@W_hh^T + biases, and cell transpose.
// ---------------------------------------------------------------------------
__global__ void prep_kernel(const float* __restrict__ hidden,
                            const float* __restrict__ cell,
                            const float* __restrict__ W_hh0,
                            const float* __restrict__ b_ih0,
                            const float* __restrict__ b_hh0,
                            const float* __restrict__ W_hh1,
                            const float* __restrict__ b_ih1,
                            const float* __restrict__ b_hh1) {
    int b = blockIdx.x * blockDim.x + threadIdx.x;
    if (b >= BB) return;

    float h0[HH], h1[HH];
#pragma unroll
    for (int k = 0; k < HH; k++) {
        h0[k] = hidden[b * HH + k];
        h1[k] = hidden[BB * HH + b * HH + k];
    }
#pragma unroll
    for (int g = 0; g < GG; g++) {
        float s0 = b_ih0[g] + b_hh0[g];
        float s1 = b_ih1[g] + b_hh1[g];
#pragma unroll
        for (int k = 0; k < HH; k++) {
            s0 = fmaf(h0[k], W_hh0[g * HH + k], s0);
            s1 = fmaf(h1[k], W_hh1[g * HH + k], s1);
        }
        g_hb0[g * BB + b] = s0;
        g_hb1[g * BB + b] = s1;
    }
#pragma unroll
    for (int k = 0; k < HH; k++) {
        g_c0[k * BB + b] = cell[b * HH + k];
        g_c1[k * BB + b] = cell[BB * HH + b * HH + k];
    }
}

// ---------------------------------------------------------------------------
// Kernel 2: main. One thread per (t, b).
//   blockIdx.x = b-chunk (16), blockIdx.y = t (64). 256 threads.
// ---------------------------------------------------------------------------
__global__ void __launch_bounds__(BLK)
decoder_kernel(const float* __restrict__ dec_x,
               const int*   __restrict__ id1,
               const int*   __restrict__ id2,
               const int*   __restrict__ id3,
               const float* __restrict__ embed,
               const float* __restrict__ W_ih0,
               const float* __restrict__ W_ih1,
               float* __restrict__ out) {
    __shared__ float sWa[GG * DD];           // W_ih0 columns 0..31  (2560 B)
    __shared__ float sW1[GG * HH];           // W_ih1 (400 B)
    __shared__ float sLut[3 * VV * GG];      // embed@W slices (2400 B)
    __shared__ float sOut[BLK * HH];         // output staging (5120 B)

    const int tid = threadIdx.x;

    // Cooperative shared fill
    for (int i = tid; i < GG * DD; i += BLK) {
        int g = i >> 5, k = i & 31;
        sWa[i] = W_ih0[g * IN + k];
    }
    for (int i = tid; i < GG * HH; i += BLK) sW1[i] = W_ih1[i];
    for (int i = tid; i < 3 * VV * GG; i += BLK) {
        int j = i / (VV * GG);
        int r = i - j * (VV * GG);
        int v = r / GG;
        int g = r - v * GG;
        const float* e = embed + v * DD;
        const float* w = W_ih0 + g * IN + DD + DD * j;
        float s = 0.0f;
#pragma unroll
        for (int k = 0; k < DD; k++) s = fmaf(e[k], w[k], s);
        sLut[i] = s;  // layout [j][v][g]
    }
    __syncthreads();

    const int b  = blockIdx.x * BLK + tid;
    const int t  = blockIdx.y;
    const int tb = t * BB + b;

    const int i1 = id1[tb];
    const int i2 = id2[tb];
    const int i3 = id3[tb];

    // Load x (32 floats, fully coalesced float4)
    float x[DD];
    {
        const float4* xp = (const float4*)(dec_x + (size_t)tb * DD);
#pragma unroll
        for (int q = 0; q < 8; q++) {
            float4 v = xp[q];
            x[4 * q + 0] = v.x; x[4 * q + 1] = v.y;
            x[4 * q + 2] = v.z; x[4 * q + 3] = v.w;
        }
    }

    // Gates layer 0: hb0 + embedding LUTs + dec_x @ Wa^T
    float acc[GG];
#pragma unroll
    for (int g = 0; g < GG; g++) {
        acc[g] = g_hb0[g * BB + b]
               + sLut[            i1 * GG + g]
               + sLut[VV * GG   + i2 * GG + g]
               + sLut[2 * VV*GG + i3 * GG + g];
    }
#pragma unroll
    for (int g = 0; g < GG; g++) {
        float s = acc[g];
#pragma unroll
        for (int k = 0; k < DD; k++) s = fmaf(x[k], sWa[g * DD + k], s);
        acc[g] = s;
    }

    // LSTM cell 0 (gate order: i, f, g, o)
    float h1[HH];
#pragma unroll
    for (int k = 0; k < HH; k++) {
        float ig = sigm(acc[k]);
        float fg = sigm(acc[HH + k]);
        float gg = tanh_(acc[2 * HH + k]);
        float og = sigm(acc[3 * HH + k]);
        float c  = fmaf(fg, g_c0[k * BB + b], ig * gg);
        h1[k] = og * tanh_(c);
    }

    // Gates layer 1: hb1 + h1 @ W_ih1^T
    float a1[GG];
#pragma unroll
    for (int g = 0; g < GG; g++) {
        float s = g_hb1[g * BB + b];
#pragma unroll
        for (int k = 0; k < HH; k++) s = fmaf(h1[k], sW1[g * HH + k], s);
        a1[g] = s;
    }

    // LSTM cell 1 -> staged output
#pragma unroll
    for (int k = 0; k < HH; k++) {
        float ig = sigm(a1[k]);
        float fg = sigm(a1[HH + k]);
        float gg = tanh_(a1[2 * HH + k]);
        float og = sigm(a1[3 * HH + k]);
        float c  = fmaf(fg, g_c1[k * BB + b], ig * gg);
        sOut[tid * HH + k] = og * tanh_(c);
    }
    __syncthreads();

    // Coalesced store of the block's [256, 5] output slab
    float* ob = out + (size_t)t * BB * HH + (size_t)blockIdx.x * BLK * HH;
    for (int i = tid; i < BLK * HH; i += BLK) ob[i] = sOut[i];
}

// ---------------------------------------------------------------------------
// Launch
// Input order (metadata): 0 horizon, 1 hidden, 2 cell, 3 dec_x, 4 mote_id_cat,
// 5 fault_type_cat, 6 mote_fault_cat, 7 mote_embed, 8 W_ih0, 9 W_hh0,
// 10 b_ih0, 11 b_hh0, 12 W_ih1, 13 W_hh1, 14 b_ih1, 15 b_hh1
// ---------------------------------------------------------------------------
extern "C" void kernel_launch(void* const* d_in, const int* in_sizes, int n_in,
                              void* d_out, int out_size) {
    const float* hidden = (const float*)d_in[1];
    const float* cell   = (const float*)d_in[2];
    const float* dec_x  = (const float*)d_in[3];
    const int*   id1    = (const int*)d_in[4];
    const int*   id2    = (const int*)d_in[5];
    const int*   id3    = (const int*)d_in[6];
    const float* embed  = (const float*)d_in[7];
    const float* W_ih0  = (const float*)d_in[8];
    const float* W_hh0  = (const float*)d_in[9];
    const float* b_ih0  = (const float*)d_in[10];
    const float* b_hh0  = (const float*)d_in[11];
    const float* W_ih1  = (const float*)d_in[12];
    const float* W_hh1  = (const float*)d_in[13];
    const float* b_ih1  = (const float*)d_in[14];
    const float* b_hh1  = (const float*)d_in[15];
    float* out = (float*)d_out;

    prep_kernel<<<BB / BLK, BLK>>>(hidden, cell, W_hh0, b_ih0, b_hh0,
                                   W_hh1, b_ih1, b_hh1);

    dim3 grid(NCHUNK, TT);
    decoder_kernel<<<grid, BLK>>>(dec_x, id1, id2, id3, embed,
                                  W_ih0, W_ih1, out);
}

// round 5
// speedup vs baseline: 1.3847x; 1.3847x over previous
#include <cuda_runtime.h>
#include <cstdint>

// Problem constants (fixed shapes from setup_inputs)
#define TT 64
#define BB 4096
#define DD 32
#define HH 5
#define GG 20      // 4*H gates
#define VV 10
#define IN 128

#define BLK 256
#define IPT 2                       // items (b values) per thread
#define BPB (BLK * IPT)             // 512 b's per block
#define NCHUNK (BB / BPB)           // 8 b-chunks

// Per-b precomputed terms (transposed [g][B] for coalesced access), L2-resident.
__device__ float g_hb0[GG * BB];
__device__ float g_hb1[GG * BB];
__device__ float g_c0[HH * BB];
__device__ float g_c1[HH * BB];

__device__ __forceinline__ float sigm(float v) {
    return __fdividef(1.0f, 1.0f + __expf(-v));
}
__device__ __forceinline__ float tanh_(float v) {
    return 1.0f - __fdividef(2.0f, __expf(2.0f * v) + 1.0f);
}

// ---------------------------------------------------------------------------
// Kernel 1: per-b precompute of h@W_hh^T + biases, and cell transpose.
// ---------------------------------------------------------------------------
__global__ void prep_kernel(const float* __restrict__ hidden,
                            const float* __restrict__ cell,
                            const float* __restrict__ W_hh0,
                            const float* __restrict__ b_ih0,
                            const float* __restrict__ b_hh0,
                            const float* __restrict__ W_hh1,
                            const float* __restrict__ b_ih1,
                            const float* __restrict__ b_hh1) {
    int b = blockIdx.x * blockDim.x + threadIdx.x;
    if (b >= BB) return;

    float h0[HH], h1[HH];
#pragma unroll
    for (int k = 0; k < HH; k++) {
        h0[k] = hidden[b * HH + k];
        h1[k] = hidden[BB * HH + b * HH + k];
    }
#pragma unroll
    for (int g = 0; g < GG; g++) {
        float s0 = b_ih0[g] + b_hh0[g];
        float s1 = b_ih1[g] + b_hh1[g];
#pragma unroll
        for (int k = 0; k < HH; k++) {
            s0 = fmaf(h0[k], W_hh0[g * HH + k], s0);
            s1 = fmaf(h1[k], W_hh1[g * HH + k], s1);
        }
        g_hb0[g * BB + b] = s0;
        g_hb1[g * BB + b] = s1;
    }
#pragma unroll
    for (int k = 0; k < HH; k++) {
        g_c0[k * BB + b] = cell[b * HH + k];
        g_c1[k * BB + b] = cell[BB * HH + b * HH + k];
    }
}

// ---------------------------------------------------------------------------
// Kernel 2: main. One thread per (t, b-pair). All shared weight reads are
// LDS.128; each weight register is reused across the 2 items.
//   blockIdx.x = b-chunk (8), blockIdx.y = t (64). 256 threads.
// ---------------------------------------------------------------------------
__global__ void __launch_bounds__(BLK)
decoder_kernel(const float* __restrict__ dec_x,
               const int*   __restrict__ id1,
               const int*   __restrict__ id2,
               const int*   __restrict__ id3,
               const float* __restrict__ embed,
               const float* __restrict__ W_ih0,
               const float* __restrict__ W_ih1,
               float* __restrict__ out) {
    __shared__ float sWa[GG * DD];          // W_ih0[:, 0:32], rows 128B (f4-read)
    __shared__ float sLut[3 * VV * GG];     // [j][v][g] rows of 20 floats (f4-read)
    __shared__ float sW1t[HH * GG];         // W_ih1 transposed [k][g] (f4-read)
    __shared__ float sOut[BPB * HH];        // output staging (10240 B)

    const int tid = threadIdx.x;

    // ---- cooperative shared fill ----
    for (int i = tid; i < GG * DD; i += BLK) {
        int g = i >> 5, k = i & 31;
        sWa[i] = W_ih0[g * IN + k];
    }
    for (int i = tid; i < HH * GG; i += BLK) {
        int k = i / GG, g = i - k * GG;
        sW1t[i] = W_ih1[g * HH + k];
    }
    for (int i = tid; i < 3 * VV * GG; i += BLK) {
        int j = i / (VV * GG);
        int r = i - j * (VV * GG);
        int v = r / GG;
        int g = r - v * GG;
        const float* e = embed + v * DD;
        const float* w = W_ih0 + g * IN + DD + DD * j;
        float s = 0.0f;
#pragma unroll
        for (int k = 0; k < DD; k++) s = fmaf(e[k], w[k], s);
        sLut[i] = s;  // layout [j][v][g]
    }
    __syncthreads();

    const int t   = blockIdx.y;
    const int b0  = blockIdx.x * BPB + tid * IPT;   // even
    const int tb0 = t * BB + b0;

    // ---- init acc with hb0 (float2 covers both items) ----
    float acc[IPT][GG];
#pragma unroll
    for (int g = 0; g < GG; g++) {
        float2 v = *(const float2*)(g_hb0 + g * BB + b0);
        acc[0][g] = v.x;
        acc[1][g] = v.y;
    }

    // ---- add embedding LUT rows (vectorized over g) ----
#pragma unroll
    for (int it = 0; it < IPT; it++) {
        const int tb = tb0 + it;
        const int i1 = id1[tb], i2 = id2[tb], i3 = id3[tb];
        const float4* l1 = (const float4*)(sLut + (0 * VV + i1) * GG);
        const float4* l2 = (const float4*)(sLut + (1 * VV + i2) * GG);
        const float4* l3 = (const float4*)(sLut + (2 * VV + i3) * GG);
#pragma unroll
        for (int q = 0; q < GG / 4; q++) {
            float4 a = l1[q], b = l2[q], c = l3[q];
            acc[it][4 * q + 0] += a.x + b.x + c.x;
            acc[it][4 * q + 1] += a.y + b.y + c.y;
            acc[it][4 * q + 2] += a.z + b.z + c.z;
            acc[it][4 * q + 3] += a.w + b.w + c.w;
        }
    }

    // ---- dec_x @ Wa^T, k-outer so each weight f4 serves both items ----
    {
        const float4* xp0 = (const float4*)(dec_x + (size_t)tb0 * DD);
        const float4* xp1 = (const float4*)(dec_x + (size_t)(tb0 + 1) * DD);
#pragma unroll
        for (int q = 0; q < DD / 4; q++) {
            float4 x0 = xp0[q];
            float4 x1 = xp1[q];
            const float4* wp = (const float4*)sWa + q;   // stride 8 f4 per gate
#pragma unroll
            for (int g = 0; g < GG; g++) {
                float4 w = wp[g * (DD / 4)];
                acc[0][g] = fmaf(x0.x, w.x, fmaf(x0.y, w.y,
                            fmaf(x0.z, w.z, fmaf(x0.w, w.w, acc[0][g]))));
                acc[1][g] = fmaf(x1.x, w.x, fmaf(x1.y, w.y,
                            fmaf(x1.z, w.z, fmaf(x1.w, w.w, acc[1][g]))));
            }
        }
    }

    // ---- LSTM cell 0 (gate order i, f, g, o) ----
    float h1[IPT][HH];
#pragma unroll
    for (int k = 0; k < HH; k++) {
        float2 c0 = *(const float2*)(g_c0 + k * BB + b0);
        float cc[IPT] = {c0.x, c0.y};
#pragma unroll
        for (int it = 0; it < IPT; it++) {
            float ig = sigm(acc[it][k]);
            float fg = sigm(acc[it][HH + k]);
            float gg = tanh_(acc[it][2 * HH + k]);
            float og = sigm(acc[it][3 * HH + k]);
            float c  = fmaf(fg, cc[it], ig * gg);
            h1[it][k] = og * tanh_(c);
        }
    }

    // ---- layer 1 gates: hb1 + h1 @ W_ih1^T (k-outer, f4 weights) ----
    float a1[IPT][GG];
#pragma unroll
    for (int g = 0; g < GG; g++) {
        float2 v = *(const float2*)(g_hb1 + g * BB + b0);
        a1[0][g] = v.x;
        a1[1][g] = v.y;
    }
#pragma unroll
    for (int k = 0; k < HH; k++) {
        const float4* wp = (const float4*)(sW1t + k * GG);
#pragma unroll
        for (int q = 0; q < GG / 4; q++) {
            float4 w = wp[q];
#pragma unroll
            for (int it = 0; it < IPT; it++) {
                float hv = h1[it][k];
                a1[it][4 * q + 0] = fmaf(hv, w.x, a1[it][4 * q + 0]);
                a1[it][4 * q + 1] = fmaf(hv, w.y, a1[it][4 * q + 1]);
                a1[it][4 * q + 2] = fmaf(hv, w.z, a1[it][4 * q + 2]);
                a1[it][4 * q + 3] = fmaf(hv, w.w, a1[it][4 * q + 3]);
            }
        }
    }

    // ---- LSTM cell 1 -> staged output ----
#pragma unroll
    for (int k = 0; k < HH; k++) {
        float2 c1 = *(const float2*)(g_c1 + k * BB + b0);
        float cc[IPT] = {c1.x, c1.y};
#pragma unroll
        for (int it = 0; it < IPT; it++) {
            float ig = sigm(a1[it][k]);
            float fg = sigm(a1[it][HH + k]);
            float gg = tanh_(a1[it][2 * HH + k]);
            float og = sigm(a1[it][3 * HH + k]);
            float c  = fmaf(fg, cc[it], ig * gg);
            sOut[(tid * IPT + it) * HH + k] = og * tanh_(c);
        }
    }
    __syncthreads();

    // ---- coalesced store of the block's [512, 5] output slab ----
    float* ob = out + (size_t)t * BB * HH + (size_t)blockIdx.x * BPB * HH;
    for (int i = tid; i < BPB * HH; i += BLK) ob[i] = sOut[i];
}

// ---------------------------------------------------------------------------
// Launch
// Input order: 0 horizon, 1 hidden, 2 cell, 3 dec_x, 4 mote_id_cat,
// 5 fault_type_cat, 6 mote_fault_cat, 7 mote_embed, 8 W_ih0, 9 W_hh0,
// 10 b_ih0, 11 b_hh0, 12 W_ih1, 13 W_hh1, 14 b_ih1, 15 b_hh1
// ---------------------------------------------------------------------------
extern "C" void kernel_launch(void* const* d_in, const int* in_sizes, int n_in,
                              void* d_out, int out_size) {
    const float* hidden = (const float*)d_in[1];
    const float* cell   = (const float*)d_in[2];
    const float* dec_x  = (const float*)d_in[3];
    const int*   id1    = (const int*)d_in[4];
    const int*   id2    = (const int*)d_in[5];
    const int*   id3    = (const int*)d_in[6];
    const float* embed  = (const float*)d_in[7];
    const float* W_ih0  = (const float*)d_in[8];
    const float* W_hh0  = (const float*)d_in[9];
    const float* b_ih0  = (const float*)d_in[10];
    const float* b_hh0  = (const float*)d_in[11];
    const float* W_ih1  = (const float*)d_in[12];
    const float* W_hh1  = (const float*)d_in[13];
    const float* b_ih1  = (const float*)d_in[14];
    const float* b_hh1  = (const float*)d_in[15];
    float* out = (float*)d_out;

    prep_kernel<<<BB / BLK, BLK>>>(hidden, cell, W_hh0, b_ih0, b_hh0,
                                   W_hh1, b_ih1, b_hh1);

    dim3 grid(NCHUNK, TT);
    decoder_kernel<<<grid, BLK>>>(dec_x, id1, id2, id3, embed,
                                  W_ih0, W_ih1, out);
}